// round 17
// baseline (speedup 1.0000x reference)
#include <cuda_runtime.h>

#define KW 7
#define PAD 3
#define H 480
#define W 640
#define NB 4
#define HW (H * W)
#define TX 32
#define TY 8
#define TILE_W (TX + 2 * PAD)   // 38
#define TILE_H (TY + 2 * PAD)   // 14
// exponent constant: -1/(2*0.1^2) * log2(e) = -50 * log2(e)
#define NEG50_LOG2E (-72.13475204444817f)

typedef unsigned long long u64;

__device__ __forceinline__ u64 pk(float lo, float hi) {
    u64 r; asm("mov.b64 %0, {%1, %2};" : "=l"(r) : "f"(lo), "f"(hi)); return r;
}
__device__ __forceinline__ void upk(float& lo, float& hi, u64 v) {
    asm("mov.b64 {%0, %1}, %2;" : "=f"(lo), "=f"(hi) : "l"(v));
}

__global__ __launch_bounds__(TX * TY, 8) void bilateral_kernel(
    const float* __restrict__ I,
    const float* __restrict__ g,
    float* __restrict__ out)
{
    __shared__ ulonglong2 tile[TILE_H][TILE_W];   // batch-interleaved, 8512 B
    __shared__ float2 lg2s[KW * KW];              // pre-broadcast log2(g), f32

    const int x0 = blockIdx.x * TX;
    const int y0 = blockIdx.y * TY;
    const int tx = threadIdx.x;
    const int ty = threadIdx.y;
    const int tid = ty * TX + tx;

    if (tid < KW * KW) {
        const float lv = __log2f(__ldg(g + tid * HW));
        lg2s[tid] = make_float2(lv, lv);
    }

    // Halo tile load (zero pad outside image), batch-interleaved.
    for (int i = tid; i < TILE_H * TILE_W; i += TX * TY) {
        const int ly = i / TILE_W;
        const int lx = i - ly * TILE_W;
        const int gy = y0 + ly - PAD;
        const int gx = x0 + lx - PAD;
        float4 v = make_float4(0.f, 0.f, 0.f, 0.f);
        if (gy >= 0 && gy < H && gx >= 0 && gx < W) {
            const int base = gy * W + gx;
            v.x = I[0 * HW + base];
            v.y = I[1 * HW + base];
            v.z = I[2 * HW + base];
            v.w = I[3 * HW + base];
        }
        *reinterpret_cast<float4*>(&tile[ly][lx]) = v;   // STS.128
    }
    __syncthreads();

    const ulonglong2 cc = tile[ty + PAD][tx + PAD];
    float c0, c1, c2, c3;
    upk(c0, c1, cc.x);
    upk(c2, c3, cc.y);
    const u64 nc01 = pk(-c0, -c1);
    const u64 nc23 = pk(-c2, -c3);
    const u64 C2 = pk(NEG50_LOG2E, NEG50_LOG2E);

    u64 num01 = 0ull, num23 = 0ull, den01 = 0ull, den23 = 0ull;

    #pragma unroll
    for (int dy = 0; dy < KW; dy++) {
        #pragma unroll
        for (int dx = 0; dx < KW; dx++) {
            const ulonglong2 s = tile[ty + dy][tx + dx];   // LDS.128
            const u64 lgb = *reinterpret_cast<const u64*>(&lg2s[dy * KW + dx]); // LDS.64 bcast

            // One fused block per tap: d = s - c; e = (C*d)*d + lg (f32x2);
            // w = 2^e via ex2.approx.f16x2; unpack with half-reg F2F; accumulate.
            asm("{\n\t"
                ".reg .b64 d0, d1, t0, t1, e0, e1, w0, w1;\n\t"
                ".reg .b32 p0, p1;\n\t"
                ".reg .b16 h0, h1, h2, h3;\n\t"
                ".reg .f32 f0, f1, f2, f3, g0, g1, g2, g3;\n\t"
                "add.rn.f32x2 d0, %4, %6;\n\t"
                "add.rn.f32x2 d1, %5, %7;\n\t"
                "mul.rn.f32x2 t0, d0, %8;\n\t"
                "mul.rn.f32x2 t1, d1, %8;\n\t"
                "fma.rn.f32x2 e0, t0, d0, %9;\n\t"
                "fma.rn.f32x2 e1, t1, d1, %9;\n\t"
                "mov.b64 {f0, f1}, e0;\n\t"
                "mov.b64 {f2, f3}, e1;\n\t"
                "cvt.rn.f16x2.f32 p0, f1, f0;\n\t"
                "cvt.rn.f16x2.f32 p1, f3, f2;\n\t"
                "ex2.approx.f16x2 p0, p0;\n\t"
                "ex2.approx.f16x2 p1, p1;\n\t"
                "mov.b32 {h0, h1}, p0;\n\t"
                "mov.b32 {h2, h3}, p1;\n\t"
                "cvt.f32.f16 g0, h0;\n\t"
                "cvt.f32.f16 g1, h1;\n\t"
                "cvt.f32.f16 g2, h2;\n\t"
                "cvt.f32.f16 g3, h3;\n\t"
                "mov.b64 w0, {g0, g1};\n\t"
                "mov.b64 w1, {g2, g3};\n\t"
                "add.rn.f32x2 %2, %2, w0;\n\t"
                "add.rn.f32x2 %3, %3, w1;\n\t"
                "fma.rn.f32x2 %0, w0, %4, %0;\n\t"
                "fma.rn.f32x2 %1, w1, %5, %1;\n\t"
                "}"
                : "+l"(num01), "+l"(num23), "+l"(den01), "+l"(den23)
                : "l"(s.x), "l"(s.y), "l"(nc01), "l"(nc23), "l"(C2), "l"(lgb));
        }
    }

    float n0, n1, n2, n3, de0, de1, de2, de3;
    upk(n0, n1, num01); upk(n2, n3, num23);
    upk(de0, de1, den01); upk(de2, de3, den23);

    const int oidx = (y0 + ty) * W + (x0 + tx);
    out[0 * HW + oidx] = __fdividef(n0, de0);
    out[1 * HW + oidx] = __fdividef(n1, de1);
    out[2 * HW + oidx] = __fdividef(n2, de2);
    out[3 * HW + oidx] = __fdividef(n3, de3);
}

extern "C" void kernel_launch(void* const* d_in, const int* in_sizes, int n_in,
                              void* d_out, int out_size)
{
    const float* I = (const float*)d_in[0];
    const float* g = (const float*)d_in[1];
    float* out = (float*)d_out;

    dim3 block(TX, TY);
    dim3 grid(W / TX, H / TY);   // 20 x 60, exact
    bilateral_kernel<<<grid, block>>>(I, g, out);
}